// round 11
// baseline (speedup 1.0000x reference)
#include <cuda_runtime.h>

// Problem constants (fixed shapes per reference)
#define KROWS 1025
#define F     8192
#define NCHUNK 128
#define ROWS_PER_CHUNK 8   // 1024/128

// Device scratch (no allocations in kernel_launch)
__device__ float g_partial[NCHUNK * F];   // 4 MB
__device__ float g_scale[F];

// Side stream + fork/join events (host objects, created at load time).
static cudaStream_t g_side;
static cudaEvent_t  g_fork, g_done;
namespace {
struct StreamInit {
    StreamInit() {
        cudaStreamCreateWithFlags(&g_side, cudaStreamNonBlocking);
        cudaEventCreateWithFlags(&g_fork, cudaEventDisableTiming);
        cudaEventCreateWithFlags(&g_done, cudaEventDisableTiming);
    }
};
StreamInit g_stream_init;
}

// Side kernel: persistent ext-block zeroing. 296 blocks (2/SM) grid-stride
// over 16384 half-row units; __stcs streaming stores (no L2 fill); skips the
// diagonal float4 (written by finalize on the main stream — disjoint bytes).
__global__ void __launch_bounds__(256) relu_z_ext_zero(float* __restrict__ out)
{
    const int tid = threadIdx.x;
    const float4 z = make_float4(0.f, 0.f, 0.f, 0.f);
    for (int u = blockIdx.x; u < 16384; u += gridDim.x) {
        int row   = u >> 1;
        int diag4 = row >> 2;
        int c0    = ((u & 1) << 10) + tid;
        float4* os = (float4*)(out + (size_t)(KROWS + row) * F);
        bool hasDiag = ((diag4 >> 10) == (u & 1)) && ((diag4 & 255) == tid);
        if (!hasDiag) {
            #pragma unroll
            for (int j = 0; j < 4; ++j) __stcs(&os[c0 + (j << 8)], z);
        } else {
            #pragma unroll
            for (int j = 0; j < 4; ++j) {
                int i = c0 + (j << 8);
                if (i != diag4) __stcs(&os[i], z);
            }
        }
    }
}

// Main 1: partial |x| column sums over rows 1..1024 (R7-proven config).
__global__ void __launch_bounds__(256) relu_z_partial_abs(
    const float* __restrict__ x)
{
    int c4    = (blockIdx.x << 8) + threadIdx.x;   // 0..F/4-1
    int chunk = blockIdx.y;                        // 0..127
    int r0 = 1 + chunk * ROWS_PER_CHUNK;

    const float4* p = (const float4*)(x + (size_t)r0 * F) + c4;
    float4 s = make_float4(0.f, 0.f, 0.f, 0.f);
    #pragma unroll
    for (int r = 0; r < ROWS_PER_CHUNK; ++r) {
        float4 v = p[(size_t)r * (F / 4)];
        s.x += fabsf(v.x);
        s.y += fabsf(v.y);
        s.z += fabsf(v.z);
        s.w += fabsf(v.w);
    }
    ((float4*)(g_partial + chunk * F))[c4] = s;
}

// Main 2: fold partials -> scale; center row + ext diagonal float4.
__global__ void __launch_bounds__(256) relu_z_finalize(
    const float* __restrict__ x,
    const float* __restrict__ lambdas,
    float* __restrict__ out)
{
    int f = blockIdx.x * blockDim.x + threadIdx.x;
    float abssum = 0.0f;
    #pragma unroll 16
    for (int c = 0; c < NCHUNK; ++c) abssum += g_partial[c * F + f];

    float ctr = x[f];                 // x[0][f]
    float l = ctr - abssum;
    float u = ctr + abssum;
    float lam = lambdas[f];

    float pos   = (l > 0.0f) ? 1.0f : 0.0f;
    float cross = ((u > 0.0f) && (l < 0.0f)) ? 1.0f : 0.0f;
    float d     = fmaxf(-l * lam, u * (1.0f - lam));
    float scale = pos + cross * lam;
    float half  = 0.5f * cross * d;

    g_scale[f] = scale;
    out[f] = scale * ctr + half;      // center row

    float4 dv = make_float4(0.f, 0.f, 0.f, 0.f);
    ((float*)&dv)[f & 3] = half;
    ((float4*)(out + (size_t)(KROWS + f) * F))[f >> 2] = dv;  // ext diagonal
}

// Main 3: body rows, out = scale * x, streaming stores.
__global__ void __launch_bounds__(256) relu_z_body(
    const float* __restrict__ x, float* __restrict__ out)
{
    const int b   = blockIdx.x;       // 0..2047 (half-row units)
    const int tid = threadIdx.x;
    int r  = 1 + (b >> 1);
    int c0 = ((b & 1) << 10) + tid;
    const float4* xs = (const float4*)(x + (size_t)r * F);
    const float4* sc = (const float4*)g_scale;
    float4* os = (float4*)(out + (size_t)r * F);
    #pragma unroll
    for (int j = 0; j < 4; ++j) {
        int i = c0 + (j << 8);
        float4 v = xs[i];
        float4 s = sc[i];
        float4 o;
        o.x = s.x * v.x;
        o.y = s.y * v.y;
        o.z = s.z * v.z;
        o.w = s.w * v.w;
        __stcs(&os[i], o);            // out never re-read: bypass L2 fill
    }
}

extern "C" void kernel_launch(void* const* d_in, const int* in_sizes, int n_in,
                              void* d_out, int out_size) {
    const float* x       = (const float*)d_in[0];
    const float* lambdas = (const float*)d_in[1];
    float* out           = (float*)d_out;

    // Fork: persistent ext zeroing (2 blocks/SM, streaming stores) runs
    // concurrently with the whole main chain.
    cudaEventRecord(g_fork, 0);
    cudaStreamWaitEvent(g_side, g_fork, 0);
    relu_z_ext_zero<<<296, 256, 0, g_side>>>(out);
    cudaEventRecord(g_done, g_side);

    // Main chain:
    {
        dim3 grid(8, NCHUNK);          // 1024 blocks
        relu_z_partial_abs<<<grid, 256>>>(x);
    }
    relu_z_finalize<<<F / 256, 256>>>(x, lambdas, out);
    relu_z_body<<<2048, 256>>>(x, out);

    // Join.
    cudaStreamWaitEvent(0, g_done, 0);
}

// round 12
// speedup vs baseline: 1.0525x; 1.0525x over previous
#include <cuda_runtime.h>

// Problem constants (fixed shapes per reference)
#define KROWS 1025
#define F     8192
#define NCHUNK 128
#define ROWS_PER_CHUNK 8   // 1024/128

// Device scratch (no allocations in kernel_launch)
__device__ float g_partial[NCHUNK * F];   // 4 MB
__device__ float g_scale[F];

// Kernel 1: partial |x| column sums over rows 1..1024.
// __ldcg loads (L1 bypass, no reuse) + 8 independent accumulators so all 8
// LDG.128s can be in flight before any dependent FADD.
__global__ void __launch_bounds__(256) relu_z_partial_abs(
    const float* __restrict__ x)
{
    const int c4    = (blockIdx.x << 8) + threadIdx.x;  // 0..F/4-1
    const int chunk = blockIdx.y;                       // 0..127
    const size_t st = F / 4;

    const float4* p = (const float4*)(x + (size_t)(1 + chunk * ROWS_PER_CHUNK) * F) + c4;
    float4 v0 = __ldcg(p + 0 * st);
    float4 v1 = __ldcg(p + 1 * st);
    float4 v2 = __ldcg(p + 2 * st);
    float4 v3 = __ldcg(p + 3 * st);
    float4 v4 = __ldcg(p + 4 * st);
    float4 v5 = __ldcg(p + 5 * st);
    float4 v6 = __ldcg(p + 6 * st);
    float4 v7 = __ldcg(p + 7 * st);

    // independent per-pair partial sums, then tree combine
    float4 a01, a23, a45, a67;
    a01.x = fabsf(v0.x) + fabsf(v1.x);
    a01.y = fabsf(v0.y) + fabsf(v1.y);
    a01.z = fabsf(v0.z) + fabsf(v1.z);
    a01.w = fabsf(v0.w) + fabsf(v1.w);
    a23.x = fabsf(v2.x) + fabsf(v3.x);
    a23.y = fabsf(v2.y) + fabsf(v3.y);
    a23.z = fabsf(v2.z) + fabsf(v3.z);
    a23.w = fabsf(v2.w) + fabsf(v3.w);
    a45.x = fabsf(v4.x) + fabsf(v5.x);
    a45.y = fabsf(v4.y) + fabsf(v5.y);
    a45.z = fabsf(v4.z) + fabsf(v5.z);
    a45.w = fabsf(v4.w) + fabsf(v5.w);
    a67.x = fabsf(v6.x) + fabsf(v7.x);
    a67.y = fabsf(v6.y) + fabsf(v7.y);
    a67.z = fabsf(v6.z) + fabsf(v7.z);
    a67.w = fabsf(v6.w) + fabsf(v7.w);

    float4 s;
    s.x = (a01.x + a23.x) + (a45.x + a67.x);
    s.y = (a01.y + a23.y) + (a45.y + a67.y);
    s.z = (a01.z + a23.z) + (a45.z + a67.z);
    s.w = (a01.w + a23.w) + (a45.w + a67.w);
    ((float4*)(g_partial + chunk * F))[c4] = s;
}

// Kernel 2: fold partials (float4-wide, L2-resident) -> scale; write center
// row + ext diagonal float4s. 8 blocks x 256 threads, 4 features per thread.
__global__ void __launch_bounds__(256) relu_z_finalize(
    const float* __restrict__ x,
    const float* __restrict__ lambdas,
    float* __restrict__ out)
{
    int c4 = blockIdx.x * blockDim.x + threadIdx.x;   // 0..2047
    const size_t st = F / 4;

    float4 acc = make_float4(0.f, 0.f, 0.f, 0.f);
    const float4* gp = (const float4*)g_partial;
    #pragma unroll 16
    for (int c = 0; c < NCHUNK; ++c) {
        float4 t = gp[(size_t)c * st + c4];
        acc.x += t.x; acc.y += t.y; acc.z += t.z; acc.w += t.w;
    }

    float4 ctr = ((const float4*)x)[c4];
    float4 lam = ((const float4*)lambdas)[c4];

    float4 scale4, center4;
    float hf[4];
    const float* ab = (const float*)&acc;
    const float* ct = (const float*)&ctr;
    const float* lm = (const float*)&lam;
    float* sc = (float*)&scale4;
    float* ce = (float*)&center4;
    #pragma unroll
    for (int k = 0; k < 4; ++k) {
        float l = ct[k] - ab[k];
        float u = ct[k] + ab[k];
        float pos   = (l > 0.0f) ? 1.0f : 0.0f;
        float cross = ((u > 0.0f) && (l < 0.0f)) ? 1.0f : 0.0f;
        float d     = fmaxf(-l * lm[k], u * (1.0f - lm[k]));
        sc[k] = pos + cross * lm[k];
        hf[k] = 0.5f * cross * d;
        ce[k] = sc[k] * ct[k] + hf[k];
    }

    ((float4*)g_scale)[c4] = scale4;
    ((float4*)out)[c4]     = center4;           // center row

    // ext diagonal: feature f = 4*c4+k sits in float4 slot c4 of ext row f
    #pragma unroll
    for (int k = 0; k < 4; ++k) {
        int f = (c4 << 2) + k;
        float4 dv = make_float4(0.f, 0.f, 0.f, 0.f);
        ((float*)&dv)[k] = hf[k];
        ((float4*)(out + (size_t)(KROWS + f) * F))[c4] = dv;
    }
}

// Kernel 3: ALL remaining stores in one launch (unchanged — at write floor).
// Unit = half a row = 1024 float4 = 256 threads x 4 float4.
//   blocks [0, 2048)     : body rows 1..1024, out = scale * x (x is L2-hot)
//   blocks [2048, 18432) : ext rows, streaming zeros, skip diagonal float4
__global__ void __launch_bounds__(256) relu_z_store_all(
    const float* __restrict__ x, float* __restrict__ out)
{
    const int b   = blockIdx.x;
    const int tid = threadIdx.x;

    if (b < 2048) {
        int r  = 1 + (b >> 1);
        int c0 = ((b & 1) << 10) + tid;
        const float4* xs = (const float4*)(x + (size_t)r * F);
        const float4* sc = (const float4*)g_scale;
        float4* os = (float4*)(out + (size_t)r * F);
        #pragma unroll
        for (int j = 0; j < 4; ++j) {
            int i = c0 + (j << 8);
            float4 v = xs[i];
            float4 s = sc[i];
            float4 o;
            o.x = s.x * v.x;
            o.y = s.y * v.y;
            o.z = s.z * v.z;
            o.w = s.w * v.w;
            __stcs(&os[i], o);             // out never re-read: bypass L2 fill
        }
    } else {
        int e     = b - 2048;
        int row   = e >> 1;
        int diag4 = row >> 2;              // float4 slot owned by finalize
        int c0    = ((e & 1) << 10) + tid;
        float4* os = (float4*)(out + (size_t)(KROWS + row) * F);
        const float4 z = make_float4(0.f, 0.f, 0.f, 0.f);

        bool hasDiag = ((diag4 >> 10) == (e & 1)) && ((diag4 & 255) == tid);
        if (!hasDiag) {
            #pragma unroll
            for (int j = 0; j < 4; ++j) __stcs(&os[c0 + (j << 8)], z);
        } else {
            #pragma unroll
            for (int j = 0; j < 4; ++j) {
                int i = c0 + (j << 8);
                if (i != diag4) __stcs(&os[i], z);
            }
        }
    }
}

extern "C" void kernel_launch(void* const* d_in, const int* in_sizes, int n_in,
                              void* d_out, int out_size) {
    const float* x       = (const float*)d_in[0];
    const float* lambdas = (const float*)d_in[1];
    float* out           = (float*)d_out;

    // 1) Partial abs-sums: 8 col-groups x 128 row-chunks = 1024 blocks
    {
        dim3 grid(8, NCHUNK);
        relu_z_partial_abs<<<grid, 256>>>(x);
    }
    // 2) Finalize: scale, center row, ext diagonal (8 blocks, float4-wide)
    relu_z_finalize<<<F / 4 / 256, 256>>>(x, lambdas, out);
    // 3) Everything else: body rows + ext zeros, one launch
    relu_z_store_all<<<2048 + 16384, 256>>>(x, out);
}

// round 13
// speedup vs baseline: 1.1419x; 1.0849x over previous
#include <cuda_runtime.h>

// Problem constants (fixed shapes per reference)
#define KROWS 1025
#define F     8192
#define NCHUNK 128
#define ROWS_PER_CHUNK 8   // 1024/128

// Device scratch (no allocations in kernel_launch)
__device__ float g_partial[NCHUNK * F];   // 4 MB
__device__ float g_scale[F];

// Kernel 1: partial |x| column sums over rows 1..1024.
// 8 col-groups x 128 row-chunks = 1024 blocks (R7-proven configuration).
__global__ void __launch_bounds__(256) relu_z_partial_abs(
    const float* __restrict__ x)
{
    int c4    = (blockIdx.x << 8) + threadIdx.x;   // 0..F/4-1
    int chunk = blockIdx.y;                        // 0..127
    int r0 = 1 + chunk * ROWS_PER_CHUNK;

    const float4* p = (const float4*)(x + (size_t)r0 * F) + c4;
    float4 s = make_float4(0.f, 0.f, 0.f, 0.f);
    #pragma unroll
    for (int r = 0; r < ROWS_PER_CHUNK; ++r) {
        float4 v = p[(size_t)r * (F / 4)];
        s.x += fabsf(v.x);
        s.y += fabsf(v.y);
        s.z += fabsf(v.z);
        s.w += fabsf(v.w);
    }
    ((float4*)(g_partial + chunk * F))[c4] = s;
}

// Kernel 2: fold the 128 partials (L2-resident) -> scale; write center row
// + ext diagonal float4. 32 blocks x 256 threads = one thread per feature
// (fold parallelism spread across 32 SMs — 8-block variants regress).
__global__ void __launch_bounds__(256) relu_z_finalize(
    const float* __restrict__ x,
    const float* __restrict__ lambdas,
    float* __restrict__ out)
{
    int f = blockIdx.x * blockDim.x + threadIdx.x;   // 0..F-1
    float abssum = 0.0f;
    #pragma unroll 16
    for (int c = 0; c < NCHUNK; ++c) abssum += __ldcg(&g_partial[c * F + f]);

    float ctr = x[f];                 // x[0][f]
    float l = ctr - abssum;
    float u = ctr + abssum;
    float lam = lambdas[f];

    float pos   = (l > 0.0f) ? 1.0f : 0.0f;
    float cross = ((u > 0.0f) && (l < 0.0f)) ? 1.0f : 0.0f;
    float d     = fmaxf(-l * lam, u * (1.0f - lam));
    float scale = pos + cross * lam;
    float half  = 0.5f * cross * d;

    g_scale[f] = scale;
    out[f] = scale * ctr + half;      // center row

    // diagonal float4 of the ext block (store_all skips this slot)
    float4 dv = make_float4(0.f, 0.f, 0.f, 0.f);
    ((float*)&dv)[f & 3] = half;
    ((float4*)(out + (size_t)(KROWS + f) * F))[f >> 2] = dv;
}

// Kernel 3: ALL remaining stores in one launch (at the 302 MB write floor).
// Unit = half a row = 1024 float4 = 256 threads x 4 float4.
//   blocks [0, 2048)     : body rows 1..1024, out = scale * x (x is L2-hot)
//   blocks [2048, 18432) : ext rows, streaming zeros, skip diagonal float4
__global__ void __launch_bounds__(256) relu_z_store_all(
    const float* __restrict__ x, float* __restrict__ out)
{
    const int b   = blockIdx.x;
    const int tid = threadIdx.x;

    if (b < 2048) {
        int r  = 1 + (b >> 1);
        int c0 = ((b & 1) << 10) + tid;
        const float4* xs = (const float4*)(x + (size_t)r * F);
        const float4* sc = (const float4*)g_scale;
        float4* os = (float4*)(out + (size_t)r * F);
        #pragma unroll
        for (int j = 0; j < 4; ++j) {
            int i = c0 + (j << 8);
            float4 v = xs[i];
            float4 s = sc[i];
            float4 o;
            o.x = s.x * v.x;
            o.y = s.y * v.y;
            o.z = s.z * v.z;
            o.w = s.w * v.w;
            __stcs(&os[i], o);             // out never re-read: bypass L2 fill
        }
    } else {
        int e     = b - 2048;
        int row   = e >> 1;
        int diag4 = row >> 2;              // float4 slot owned by finalize
        int c0    = ((e & 1) << 10) + tid;
        float4* os = (float4*)(out + (size_t)(KROWS + row) * F);
        const float4 z = make_float4(0.f, 0.f, 0.f, 0.f);

        // diag4 lies in this half-row iff bit 10 matches; only the thread
        // whose low 8 bits match can collide -> single hoisted branch.
        bool hasDiag = ((diag4 >> 10) == (e & 1)) && ((diag4 & 255) == tid);
        if (!hasDiag) {
            #pragma unroll
            for (int j = 0; j < 4; ++j) __stcs(&os[c0 + (j << 8)], z);
        } else {
            #pragma unroll
            for (int j = 0; j < 4; ++j) {
                int i = c0 + (j << 8);
                if (i != diag4) __stcs(&os[i], z);
            }
        }
    }
}

extern "C" void kernel_launch(void* const* d_in, const int* in_sizes, int n_in,
                              void* d_out, int out_size) {
    const float* x       = (const float*)d_in[0];
    const float* lambdas = (const float*)d_in[1];
    float* out           = (float*)d_out;

    // 1) Partial abs-sums: 8 col-groups x 128 row-chunks = 1024 blocks
    {
        dim3 grid(8, NCHUNK);
        relu_z_partial_abs<<<grid, 256>>>(x);
    }
    // 2) Finalize: scale, center row, ext diagonal (32 blocks)
    relu_z_finalize<<<F / 256, 256>>>(x, lambdas, out);
    // 3) Everything else: body rows + ext zeros, one launch
    relu_z_store_all<<<2048 + 16384, 256>>>(x, out);
}